// round 14
// baseline (speedup 1.0000x reference)
#include <cuda_runtime.h>
#include <cuda_fp16.h>
#include <cstdint>

#define T_TOK   2048
#define HID     2048
#define NEXP    64
#define INTER   512
#define SINTER  1024
#define TOPK    8
#define ROWS_SHARED 4096
#define ROWS_MOE    (T_TOK*TOPK)
#define ROWS_TOTAL  (ROWS_SHARED + ROWS_MOE)

#define SA   72   // stage1 A smem row stride (halves): K=64 + pad 8
#define SB1  72   // stage1 B row stride (halves)
#define SA2  40   // stage2 A row stride (halves): K=32 + pad 8
#define SB2  136  // stage2 B row stride (halves)

#define S1_ASTG (128*SA*2)
#define S1_BSTG (64*SB1*2)
#define S2_AST2 (128*SA2*2)
#define S2_BST2 (32*SB2*2)

// segment sizes in float4 units
#define NX4   ((long)T_TOK*HID/4)
#define NWG4  ((long)NEXP*HID*INTER/4)
#define NSG4  ((long)HID*SINTER/4)
#define NWD4  ((long)NEXP*INTER*HID/4)
#define NSD4  ((long)SINTER*HID/4)
#define NOUT4 ((long)T_TOK*HID/4)

// ---------------- device scratch ----------------
__device__ float    g_logits[T_TOK*NEXP];
__device__ int      g_sel  [T_TOK*TOPK];
__device__ float    g_selw [T_TOK*TOPK];
__device__ int      g_cnt  [NEXP];
__device__ int      g_off  [NEXP];
__device__ int      g_tok  [ROWS_MOE];
__device__ float    g_tw   [ROWS_MOE];
__device__ __half   g_Hh[(size_t)ROWS_TOTAL*INTER];
__device__ __half   g_x16[(size_t)T_TOK*HID];
__device__ __half   g_wg16[(size_t)NEXP*HID*INTER];
__device__ __half   g_wu16[(size_t)NEXP*HID*INTER];
__device__ __half   g_wd16[(size_t)NEXP*INTER*HID];
__device__ __half   g_sg16[(size_t)HID*SINTER];
__device__ __half   g_su16[(size_t)HID*SINTER];
__device__ __half   g_sd16[(size_t)SINTER*HID];

// ---------------- helpers ----------------
__device__ __forceinline__ uint32_t smem_u32(const void* p) {
    uint32_t a;
    asm("{ .reg .u64 t; cvta.to.shared.u64 t, %1; cvt.u32.u64 %0, t; }" : "=r"(a) : "l"(p));
    return a;
}
__device__ __forceinline__ uint32_t packh2(float x, float y) {
    __half2 h = __floats2half2_rn(x, y);
    return *(uint32_t*)&h;
}
__device__ __forceinline__ void mma16(float c[4], const uint32_t a[4],
                                      uint32_t b0, uint32_t b1) {
    asm volatile(
        "mma.sync.aligned.m16n8k16.row.col.f32.f16.f16.f32 "
        "{%0,%1,%2,%3}, {%4,%5,%6,%7}, {%8,%9}, {%0,%1,%2,%3};\n"
        : "+f"(c[0]), "+f"(c[1]), "+f"(c[2]), "+f"(c[3])
        : "r"(a[0]), "r"(a[1]), "r"(a[2]), "r"(a[3]), "r"(b0), "r"(b1));
}
__device__ __forceinline__ void ldsm_x4(uint32_t r[4], uint32_t addr) {
    asm volatile("ldmatrix.sync.aligned.m8n8.x4.shared.b16 {%0,%1,%2,%3}, [%4];"
        : "=r"(r[0]), "=r"(r[1]), "=r"(r[2]), "=r"(r[3]) : "r"(addr));
}
__device__ __forceinline__ void ldsm_x4t(uint32_t r[4], uint32_t addr) {
    asm volatile("ldmatrix.sync.aligned.m8n8.x4.trans.shared.b16 {%0,%1,%2,%3}, [%4];"
        : "=r"(r[0]), "=r"(r[1]), "=r"(r[2]), "=r"(r[3]) : "r"(addr));
}
__device__ __forceinline__ void red_add_v2(float* p, float a, float b) {
    asm volatile("red.global.add.v2.f32 [%0], {%1, %2};"
        :: "l"(p), "f"(a), "f"(b) : "memory");
}
__device__ __forceinline__ void cp16(uint32_t dst, const void* src) {
    asm volatile("cp.async.cg.shared.global [%0], [%1], 16;"
        :: "r"(dst), "l"(src) : "memory");
}
#define CP_COMMIT() asm volatile("cp.async.commit_group;" ::: "memory")
#define CP_WAIT1()  asm volatile("cp.async.wait_group 1;"  ::: "memory")
#define CP_WAIT4()  asm volatile("cp.async.wait_group 4;"  ::: "memory")

__device__ __forceinline__ uint2 cvt4(const float4 v) {
    return make_uint2(packh2(v.x, v.y), packh2(v.z, v.w));
}

// ---------------- 1) router GEMM (blocks 0-63) + conversions (blocks 64+) --
__global__ void router_cvt(const float* __restrict__ xf,
                           const float* __restrict__ rw,
                           const float4* __restrict__ wg,
                           const float4* __restrict__ wu,
                           const float4* __restrict__ wd,
                           const float4* __restrict__ sg,
                           const float4* __restrict__ su,
                           const float4* __restrict__ sd,
                           float4* __restrict__ out) {
    if (blockIdx.x >= 64) {
        const long i0 = (long)(blockIdx.x - 64)*blockDim.x + threadIdx.x;
        const long st = (long)(gridDim.x - 64)*blockDim.x;
        const float4* x4 = (const float4*)xf;
        uint2* xd  = (uint2*)g_x16;
        uint2* wgd = (uint2*)g_wg16;
        uint2* wud = (uint2*)g_wu16;
        uint2* wdd = (uint2*)g_wd16;
        uint2* sgd = (uint2*)g_sg16;
        uint2* sud = (uint2*)g_su16;
        uint2* sdd = (uint2*)g_sd16;
        for (long i = i0; i < NX4;  i += st) xd[i]  = cvt4(x4[i]);
        for (long i = i0; i < NWG4; i += st) wgd[i] = cvt4(wg[i]);
        for (long i = i0; i < NWG4; i += st) wud[i] = cvt4(wu[i]);
        for (long i = i0; i < NWD4; i += st) wdd[i] = cvt4(wd[i]);
        for (long i = i0; i < NSG4; i += st) sgd[i] = cvt4(sg[i]);
        for (long i = i0; i < NSG4; i += st) sud[i] = cvt4(su[i]);
        for (long i = i0; i < NSD4; i += st) sdd[i] = cvt4(sd[i]);
        for (long i = i0; i < NOUT4; i += st) out[i] = make_float4(0.f,0.f,0.f,0.f);
        return;
    }
    __shared__ float As[32][33];
    __shared__ float Bs[32][65];
    const int tid = threadIdx.x;
    const int t0  = blockIdx.x * 32;
    const int m   = tid >> 3, nb = tid & 7;
    float acc[8] = {};
    for (int kt = 0; kt < HID; kt += 32) {
        __syncthreads();
        {   int r = tid >> 3, c = (tid & 7) * 4;
            const float4 v = *(const float4*)(xf + (size_t)(t0 + r)*HID + kt + c);
            As[r][c] = v.x; As[r][c+1] = v.y; As[r][c+2] = v.z; As[r][c+3] = v.w; }
        #pragma unroll
        for (int i = 0; i < 8; i++) {
            int idx = tid + i*256; int e = idx >> 5, k = idx & 31;
            Bs[k][e] = rw[(size_t)e*HID + kt + k];
        }
        __syncthreads();
        #pragma unroll
        for (int k = 0; k < 32; k++) {
            float a = As[m][k];
            #pragma unroll
            for (int j = 0; j < 8; j++) acc[j] += a * Bs[k][nb + 8*j];
        }
    }
    #pragma unroll
    for (int j = 0; j < 8; j++) g_logits[(size_t)(t0+m)*NEXP + nb + 8*j] = acc[j];
}

// ---------------- 2) fused routing: topk + scan + scatter, one block -------
__global__ void __launch_bounds__(512)
routing_kernel() {
    __shared__ int scnt[NEXP];
    __shared__ int soff[NEXP];
    const int tid = threadIdx.x;
    if (tid < NEXP) scnt[tid] = 0;
    __syncthreads();

    #pragma unroll 1
    for (int t = tid; t < T_TOK; t += 512) {
        float l[NEXP];
        #pragma unroll
        for (int e = 0; e < NEXP; e++) l[e] = g_logits[(size_t)t*NEXP + e];
        float bw[TOPK]; int bi[TOPK];
        for (int i = 0; i < TOPK; i++) {
            float mv = -1e30f; int mi = 0;
            for (int e = 0; e < NEXP; e++) if (l[e] > mv) { mv = l[e]; mi = e; }
            bw[i] = mv; bi[i] = mi; l[mi] = -1e30f;
        }
        float s = 0.f, mx = bw[0], w[TOPK];
        #pragma unroll
        for (int i = 0; i < TOPK; i++) { w[i] = expf(bw[i] - mx); s += w[i]; }
        float inv = 1.f / s;
        #pragma unroll
        for (int i = 0; i < TOPK; i++) {
            g_sel [t*TOPK+i] = bi[i];
            g_selw[t*TOPK+i] = w[i]*inv;
            atomicAdd(&scnt[bi[i]], 1);
        }
    }
    __syncthreads();

    if (tid == 0) {
        int o = 0;
        for (int e = 0; e < NEXP; e++) { soff[e] = o; o += scnt[e]; }
    }
    __syncthreads();
    if (tid < NEXP) {
        g_cnt[tid] = scnt[tid];
        g_off[tid] = soff[tid];
        scnt[tid]  = soff[tid];   // reuse as cursor
    }
    __syncthreads();

    #pragma unroll 1
    for (int idx = tid; idx < T_TOK*TOPK; idx += 512) {
        int e = g_sel[idx];
        int pos = atomicAdd(&scnt[e], 1);
        g_tok[pos] = idx >> 3;
        g_tw [pos] = g_selw[idx];
    }
}

// ---------------- 4) stage 1: R9 champion (3-stage, K-tile 64) -------------
// grid (16, 66, 8); CTA M=128, N=64g+64u, 128 threads
#define S1_A    1024
#define S1_BG   (S1_A  + 3*S1_ASTG)
#define S1_BU   (S1_BG + 3*S1_BSTG)
#define S1_SMEM (S1_BU + 3*S1_BSTG)
__global__ void __launch_bounds__(128, 2)
stage1_kernel() {
    const int s = blockIdx.y;
    int nrows, hbase, ldb, offmoe = 0;
    const __half *Bg, *Bu;
    if (s < 2) {
        nrows = T_TOK; hbase = s*T_TOK; ldb = SINTER;
        Bg = g_sg16 + s*INTER; Bu = g_su16 + s*INTER;
    } else {
        int e = s - 2;
        nrows = g_cnt[e]; offmoe = g_off[e]; hbase = ROWS_SHARED + offmoe; ldb = INTER;
        Bg = g_wg16 + (size_t)e*HID*INTER; Bu = g_wu16 + (size_t)e*HID*INTER;
    }
    const int m0 = blockIdx.x * 128;
    if (m0 >= nrows) return;
    const int n0   = blockIdx.z * 64;
    const int nloc = nrows - m0;

    extern __shared__ char smraw[];
    int*    s_tok = (int*)smraw;
    float*  s_w   = (float*)(smraw + 512);
    const uint32_t aB  = smem_u32(smraw + S1_A);
    const uint32_t bgB = smem_u32(smraw + S1_BG);
    const uint32_t buB = smem_u32(smraw + S1_BU);

    const int tid = threadIdx.x;
    {
        int r = m0 + tid;
        if (r < nrows) {
            if (s < 2) { s_tok[tid] = r; s_w[tid] = 1.f; }
            else       { s_tok[tid] = g_tok[offmoe + r]; s_w[tid] = g_tw[offmoe + r]; }
        } else { s_tok[tid] = (s < 2) ? 0 : g_tok[offmoe]; s_w[tid] = 0.f; }
    }
    __syncthreads();

    const int lane = tid & 31, warp = tid >> 5;
    const int wm = warp >> 1, wn = warp & 1;
    const int l4 = lane >> 2, lq = lane & 3;
    const int lr = lane & 15, lc = lane >> 4;
    float cg[4][4][4] = {}, cu[4][4][4] = {};

    const uint32_t aFrag = aB  + (uint32_t)(wm*64 + lr)*(SA*2) + lc*16;
    const uint32_t gFrag = bgB + (uint32_t)lr*(SB1*2) + wn*64 + lc*16;
    const uint32_t uFrag = buB + (uint32_t)lr*(SB1*2) + wn*64 + lc*16;

    const int arow = tid >> 3, acol = (tid & 7)*8;
    const __half* srcA[8];
    uint32_t dA[8];
    #pragma unroll
    for (int i = 0; i < 8; i++) {
        srcA[i] = g_x16 + (size_t)s_tok[arow + 16*i]*HID + acol;
        dA[i]   = aB + (uint32_t)((arow + 16*i)*SA + acol)*2;
    }
    const __half* srcG[4]; const __half* srcU[4];
    uint32_t dG[4], dU[4];
    #pragma unroll
    for (int i = 0; i < 4; i++) {
        int br = arow + 16*i;
        srcG[i] = Bg + (size_t)br*ldb + n0 + acol;
        srcU[i] = Bu + (size_t)br*ldb + n0 + acol;
        dG[i] = bgB + (uint32_t)(br*SB1 + acol)*2;
        dU[i] = buB + (uint32_t)(br*SB1 + acol)*2;
    }

    const int NT = HID / 64;
    auto issue = [&](int tile) {
        int st = tile % 3, kt = tile * 64;
        #pragma unroll
        for (int i = 0; i < 8; i++) cp16(dA[i] + st*S1_ASTG, srcA[i] + kt);
        #pragma unroll
        for (int i = 0; i < 4; i++) {
            cp16(dG[i] + st*S1_BSTG, srcG[i] + (size_t)kt*ldb);
            cp16(dU[i] + st*S1_BSTG, srcU[i] + (size_t)kt*ldb);
        }
    };
    auto comp = [&](int st) {
        const uint32_t aOff = aFrag + (uint32_t)st*S1_ASTG;
        const uint32_t gOff = gFrag + (uint32_t)st*S1_BSTG;
        const uint32_t uOff = uFrag + (uint32_t)st*S1_BSTG;
        #pragma unroll
        for (int ks = 0; ks < 4; ks++) {
            uint32_t a[4][4], bg[2][4], bu[2][4];
            #pragma unroll
            for (int mi = 0; mi < 4; mi++)
                ldsm_x4(a[mi], aOff + mi*16*(SA*2) + ks*32);
            #pragma unroll
            for (int ni = 0; ni < 2; ni++) {
                ldsm_x4t(bg[ni], gOff + ks*16*(SB1*2) + ni*32);
                ldsm_x4t(bu[ni], uOff + ks*16*(SB1*2) + ni*32);
            }
            #pragma unroll
            for (int mi = 0; mi < 4; mi++)
                #pragma unroll
                for (int ni = 0; ni < 2; ni++) {
                    mma16(cg[mi][2*ni],   a[mi], bg[ni][0], bg[ni][1]);
                    mma16(cg[mi][2*ni+1], a[mi], bg[ni][2], bg[ni][3]);
                    mma16(cu[mi][2*ni],   a[mi], bu[ni][0], bu[ni][1]);
                    mma16(cu[mi][2*ni+1], a[mi], bu[ni][2], bu[ni][3]);
                }
        }
    };

    issue(0); CP_COMMIT();
    issue(1); CP_COMMIT();
    #pragma unroll 1
    for (int it = 0; it < NT; it++) {
        CP_WAIT1();
        __syncthreads();
        if (it + 2 < NT) issue(it + 2);
        CP_COMMIT();
        comp(it % 3);
    }

    #pragma unroll
    for (int mi = 0; mi < 4; mi++) {
        int r0 = wm*64 + mi*16 + l4;
        int r1 = r0 + 8;
        float w0 = (r0 < nloc) ? s_w[r0] : 0.f;
        float w1 = (r1 < nloc) ? s_w[r1] : 0.f;
        #pragma unroll
        for (int nj = 0; nj < 4; nj++) {
            int c = wn*32 + nj*8 + 2*lq;
            if (r0 < nloc) {
                float g0 = cg[mi][nj][0], u0 = cu[mi][nj][0];
                float g1 = cg[mi][nj][1], u1 = cu[mi][nj][1];
                float h0 = g0 / (1.f + __expf(-g0)) * u0 * w0;
                float h1 = g1 / (1.f + __expf(-g1)) * u1 * w0;
                *(uint32_t*)(g_Hh + (size_t)(hbase + m0 + r0)*INTER + n0 + c) = packh2(h0, h1);
            }
            if (r1 < nloc) {
                float g2 = cg[mi][nj][2], u2 = cu[mi][nj][2];
                float g3 = cg[mi][nj][3], u3 = cu[mi][nj][3];
                float h2 = g2 / (1.f + __expf(-g2)) * u2 * w1;
                float h3 = g3 / (1.f + __expf(-g3)) * u3 * w1;
                *(uint32_t*)(g_Hh + (size_t)(hbase + m0 + r1)*INTER + n0 + c) = packh2(h2, h3);
            }
        }
    }
}

// ---------------- 5) stage 2: L2-friendly 2D-tiled grid, fused combine -----
// grid (64, 66, 4); x = m + 16*nsub, n0 = (z*4+nsub)*128; 128 threads
#define S2_A    512
#define S2_B    (S2_A + 6*S2_AST2)
#define S2_SMEM (S2_B + 6*S2_BST2)
__global__ void __launch_bounds__(128, 2)
stage2_kernel(float* __restrict__ out) {
    const int s = blockIdx.y;
    int nrows, hbase, offmoe = 0; const __half* Bd;
    if (s < 2) { nrows = T_TOK; hbase = s*T_TOK; Bd = g_sd16 + (size_t)s*INTER*HID; }
    else { int e = s-2; nrows = g_cnt[e]; offmoe = g_off[e]; hbase = ROWS_SHARED + offmoe;
           Bd = g_wd16 + (size_t)e*INTER*HID; }
    const int m0 = (blockIdx.x & 15) * 128;
    if (m0 >= nrows) return;
    const int nsub = blockIdx.x >> 4;
    const int n0   = (blockIdx.z * 4 + nsub) * 128;
    const int nloc = nrows - m0;

    extern __shared__ char smraw[];
    int* s_tok = (int*)smraw;
    const uint32_t aB = smem_u32(smraw + S2_A);
    const uint32_t bB = smem_u32(smraw + S2_B);

    const int tid = threadIdx.x, lane = tid & 31, warp = tid >> 5;
    {
        int r = m0 + tid;
        if (r < nrows) s_tok[tid] = (s < 2) ? r : g_tok[offmoe + r];
        else           s_tok[tid] = 0;
    }
    __syncthreads();

    const int wm = warp >> 1, wn = warp & 1;
    const int l4 = lane >> 2, lq = lane & 3;
    const int lr = lane & 15, lc = lane >> 4;
    float cc[4][8][4] = {};

    const uint32_t aFrag = aB + (uint32_t)(wm*64 + lr)*(SA2*2) + lc*16;
    const uint32_t bFrag = bB + (uint32_t)lr*(SB2*2) + wn*128 + lc*16;

    const int arow = tid >> 2, acol = (tid & 3)*8;
    const int brow = tid >> 4, bcol = (tid & 15)*8;
    const __half* srcA[4];
    uint32_t dA[4];
    #pragma unroll
    for (int i = 0; i < 4; i++) {
        int r = arow + 32*i;
        int rr = (r < nloc) ? r : 0;
        srcA[i] = g_Hh + (size_t)(hbase + m0 + rr)*INTER + acol;
        dA[i]   = aB + (uint32_t)(r*SA2 + acol)*2;
    }
    const __half* srcB[4];
    uint32_t dB[4];
    #pragma unroll
    for (int i = 0; i < 4; i++) {
        int r = brow + 8*i;
        srcB[i] = Bd + (size_t)r*HID + n0 + bcol;
        dB[i]   = bB + (uint32_t)(r*SB2 + bcol)*2;
    }

    const int NT = INTER / 32;
    auto issue = [&](int tile) {
        int st = tile % 6, kt = tile * 32;
        #pragma unroll
        for (int i = 0; i < 4; i++) cp16(dA[i] + st*S2_AST2, srcA[i] + kt);
        #pragma unroll
        for (int i = 0; i < 4; i++) cp16(dB[i] + st*S2_BST2, srcB[i] + (size_t)kt*HID);
    };
    auto comp = [&](int st) {
        const uint32_t aOff = aFrag + (uint32_t)st*S2_AST2;
        const uint32_t bOff = bFrag + (uint32_t)st*S2_BST2;
        #pragma unroll
        for (int ks = 0; ks < 2; ks++) {
            uint32_t a[4][4], b[4][4];
            #pragma unroll
            for (int mi = 0; mi < 4; mi++)
                ldsm_x4(a[mi], aOff + mi*16*(SA2*2) + ks*32);
            #pragma unroll
            for (int ni = 0; ni < 4; ni++)
                ldsm_x4t(b[ni], bOff + ks*16*(SB2*2) + ni*32);
            #pragma unroll
            for (int mi = 0; mi < 4; mi++)
                #pragma unroll
                for (int ni = 0; ni < 4; ni++) {
                    mma16(cc[mi][2*ni],   a[mi], b[ni][0], b[ni][1]);
                    mma16(cc[mi][2*ni+1], a[mi], b[ni][2], b[ni][3]);
                }
        }
    };

    issue(0); CP_COMMIT();
    issue(1); CP_COMMIT();
    issue(2); CP_COMMIT();
    issue(3); CP_COMMIT();
    issue(4); CP_COMMIT();
    #pragma unroll 1
    for (int it = 0; it < NT; it++) {
        CP_WAIT4();
        __syncthreads();
        if (it + 5 < NT) issue(it + 5);
        CP_COMMIT();
        comp(it % 6);
    }

    #pragma unroll
    for (int mi = 0; mi < 4; mi++) {
        int r0 = wm*64 + mi*16 + l4;
        int r1 = r0 + 8;
        int tk0 = s_tok[r0], tk1 = s_tok[r1];
        #pragma unroll
        for (int nj = 0; nj < 8; nj++) {
            int c = n0 + wn*64 + nj*8 + 2*lq;
            if (r0 < nloc)
                red_add_v2(out + (size_t)tk0*HID + c, cc[mi][nj][0], cc[mi][nj][1]);
            if (r1 < nloc)
                red_add_v2(out + (size_t)tk1*HID + c, cc[mi][nj][2], cc[mi][nj][3]);
        }
    }
}

// ---------------- launch ----------------
extern "C" void kernel_launch(void* const* d_in, const int* in_sizes, int n_in,
                              void* d_out, int out_size) {
    const float* x  = (const float*)d_in[0];
    const float* rw = (const float*)d_in[1];
    const float* wg = (const float*)d_in[2];
    const float* wu = (const float*)d_in[3];
    const float* wd = (const float*)d_in[4];
    const float* sg = (const float*)d_in[5];
    const float* su = (const float*)d_in[6];
    const float* sd = (const float*)d_in[7];
    float* out = (float*)d_out;

    static bool attr_done = false;
    if (!attr_done) {
        cudaFuncSetAttribute(stage1_kernel, cudaFuncAttributeMaxDynamicSharedMemorySize, S1_SMEM);
        cudaFuncSetAttribute(stage2_kernel, cudaFuncAttributeMaxDynamicSharedMemorySize, S2_SMEM);
        attr_done = true;
    }

    router_cvt    <<<64 + 4032, 256>>>(x, rw,
                                       (const float4*)wg, (const float4*)wu,
                                       (const float4*)wd, (const float4*)sg,
                                       (const float4*)su, (const float4*)sd,
                                       (float4*)out);
    routing_kernel<<<1, 512>>>();
    stage1_kernel <<<dim3(16, 66, 8), 128, S1_SMEM>>>();
    stage2_kernel <<<dim3(64, 66, 4), 128, S2_SMEM>>>(out);
}